// round 6
// baseline (speedup 1.0000x reference)
#include <cuda_runtime.h>

#define NB   4096
#define NT   24
#define NN   7
#define DYN  6
#define STAT 5
#define NIN  11
#define H    64
#define FUT  48
#define G4   256
#define NTHREADS 512

typedef unsigned long long u64;

struct alignas(16) Smem {
    float enc_w[NIN * H];     // 704
    float dw1[H * 32];        // 2048
    float dw2[32 * DYN];      // 192
    float enc_b[H];
    float g1b[H];
    float g2b[H];
    float bsum[G4];
    float db1[32];
    float db2[8];
    float adjn[2][56];        // 7 rows padded to 8 (pad col stores d_i)
    float xs[2][80];
    float bufA[2][NN * H];
    float bufB[2][NN * H];
    float hx[2][NN * H];
    float cx[2][NN * H];
    float gbuf[2][NN * G4];
    float dbuf[2][NN * 32];
    float pred[2][48];
    float stat[2][40];
};

__device__ __forceinline__ float sigf(float x) {
    return 1.0f / (1.0f + __expf(-x));
}
__device__ __forceinline__ float tanhfast(float x) {
    return 2.0f / (1.0f + __expf(-2.0f * x)) - 1.0f;
}

__device__ __forceinline__ u64 fma2(u64 a, u64 b, u64 c) {
    u64 d;
    asm("fma.rn.f32x2 %0, %1, %2, %3;" : "=l"(d) : "l"(a), "l"(b), "l"(c));
    return d;
}
__device__ __forceinline__ u64 pk2(float lo, float hi) {
    u64 v;
    asm("mov.b64 %0, {%1, %2};" : "=l"(v) : "f"(lo), "f"(hi));
    return v;
}
__device__ __forceinline__ u64 pk2b(float s) { return pk2(s, s); }
__device__ __forceinline__ float2 up2(u64 v) {
    float2 f;
    asm("mov.b64 {%0, %1}, %2;" : "=f"(f.x), "=f"(f.y) : "l"(v));
    return f;
}

__global__ void __launch_bounds__(NTHREADS, 1) stgnn_kernel(
    const float* __restrict__ x_history, const float* __restrict__ adj,
    const float* __restrict__ enc_w, const float* __restrict__ enc_b,
    const float* __restrict__ g1w, const float* __restrict__ g1b,
    const float* __restrict__ g2w, const float* __restrict__ g2b,
    const float* __restrict__ w_ih, const float* __restrict__ w_hh,
    const float* __restrict__ b_ih, const float* __restrict__ b_hh,
    const float* __restrict__ dw1, const float* __restrict__ db1,
    const float* __restrict__ dw2, const float* __restrict__ db2,
    float* __restrict__ out)
{
    extern __shared__ unsigned char smraw[];
    Smem* S = reinterpret_cast<Smem*>(smraw);

    const int tid  = threadIdx.x;
    const int lane = tid & 31;
    const int wrp  = tid >> 5;
    const size_t b0 = (size_t)blockIdx.x * 2;

    // ---- stage small weights ----
    for (int i = tid; i < NIN * H; i += NTHREADS) S->enc_w[i] = enc_w[i];
    for (int i = tid; i < H * 32; i += NTHREADS) S->dw1[i] = dw1[i];
    if (tid < 32 * DYN) S->dw2[tid] = dw2[tid];
    if (tid < H)  { S->enc_b[tid] = enc_b[tid]; S->g1b[tid] = g1b[tid]; S->g2b[tid] = g2b[tid]; }
    if (tid < G4) S->bsum[tid] = b_ih[tid] + b_hh[tid];
    if (tid < 32)  S->db1[tid] = db1[tid];
    if (tid < DYN) S->db2[tid] = db2[tid];

    // ---- adjacency (both batches) ----
    if (tid < 98) {
        int bb = tid / 49, e = tid % 49, i = e / 7, j = e % 7;
        float v = adj[(b0 + bb) * 49 + e];
        if (i == j) v = 1.0f;
        S->adjn[bb][i * 8 + j] = v;
    }
    __syncthreads();
    if (tid < 14) {
        int bb = tid / 7, i = tid % 7;
        float s = 0.f;
        #pragma unroll
        for (int j = 0; j < 7; j++) s += S->adjn[bb][i * 8 + j];
        S->adjn[bb][i * 8 + 7] = rsqrtf(fmaxf(s, 1.0f));  // stash d_i in pad slot
    }
    __syncthreads();
    // Normalize: thread (i,j) reads only pad slots (written before the barrier
    // above) and its own element; writes only its own element. No barrier
    // needed inside this stage, and none is legal under the tid<98 guard.
    if (tid < 98) {
        int bb = tid / 49, e = tid % 49, i = e / 7, j = e % 7;
        S->adjn[bb][i * 8 + j] *= S->adjn[bb][i * 8 + 7] * S->adjn[bb][j * 8 + 7];
    }

    // ---- init state ----
    for (int i = tid; i < 2 * NN * H; i += NTHREADS) {
        (&S->hx[0][0])[i] = 0.f;
        (&S->cx[0][0])[i] = 0.f;
    }
    if (tid < 154) {
        int bb = tid / 77, t = tid % 77, n = t / NIN, k = t % NIN;
        float v = x_history[((b0 + bb) * NT + (NT - 1)) * 77 + t];
        if (k < DYN) S->pred[bb][n * DYN + k] = v;
        else         S->stat[bb][n * STAT + (k - DYN)] = v;
    }

    // ---- register-cache LSTM weights (64 floats = 32 packed) ----
    const int col = wrp * 16 + (lane >> 1);   // 0..255
    const int par = lane & 1;                 // 0: w_ih/s2, 1: w_hh/hx
    u64 wl[32];
    {
        const ulonglong2* wp = reinterpret_cast<const ulonglong2*>(
            (par ? w_hh : w_ih) + (size_t)col * H);
        #pragma unroll
        for (int q = 0; q < 16; q++) {
            ulonglong2 v = wp[q];
            wl[2 * q] = v.x; wl[2 * q + 1] = v.y;
        }
    }

    // ---- register-cache GCN weights (8-way K split per column) ----
    const int kq8 = tid & 7;     // K chunk of 8
    const int c8  = tid >> 3;    // column 0..63
    u64 w1p[4], w2p[4];
    #pragma unroll
    for (int q = 0; q < 4; q++) {
        int k = kq8 * 8 + 2 * q;
        w1p[q] = pk2(g1w[k * H + c8], g1w[(k + 1) * H + c8]);
        w2p[q] = pk2(g2w[k * H + c8], g2w[(k + 1) * H + c8]);
    }
    __syncthreads();

    // pair-element mapping for 448-slot phases
    const int pbb = (tid < 448) ? (tid / 224) : 0;
    const int pr  = (tid < 448) ? (tid % 224) : 0;
    const int pn  = pr >> 5;          // node
    const int php = pr & 31;          // h pair -> h = 2*php

    for (int step = 0; step < NT + FUT; ++step) {
        // ---- build x_t ----
        if (tid < 154) {
            int bb = tid / 77, t = tid % 77;
            if (step < NT) {
                S->xs[bb][t] = x_history[((b0 + bb) * NT + step) * 77 + t];
            } else {
                int n = t / NIN, k = t % NIN;
                S->xs[bb][t] = (k < DYN) ? S->pred[bb][n * DYN + k]
                                         : S->stat[bb][n * STAT + (k - DYN)];
            }
        }
        __syncthreads();

        // ---- encoder: relu(x @ enc_w + b) -> bufA ----
        if (tid < 448) {
            u64 acc = *(const u64*)(S->enc_b + 2 * php);
            const float* xr = S->xs[pbb] + pn * NIN;
            #pragma unroll
            for (int k = 0; k < NIN; k++)
                acc = fma2(pk2b(xr[k]), *(const u64*)(S->enc_w + k * H + 2 * php), acc);
            float2 a = up2(acc);
            a.x = fmaxf(a.x, 0.f); a.y = fmaxf(a.y, 0.f);
            *(float2*)(S->bufA[pbb] + pn * H + 2 * php) = a;
        }
        __syncthreads();

        // ---- gcn1 GEMM: bufA @ g1w -> bufB (register weights) ----
        #pragma unroll
        for (int bb = 0; bb < 2; bb++) {
            #pragma unroll
            for (int n = 0; n < 7; n++) {
                const ulonglong2* xp = reinterpret_cast<const ulonglong2*>(
                    S->bufA[bb] + n * H + kq8 * 8);
                ulonglong2 v0 = xp[0], v1 = xp[1];
                u64 a0 = fma2(v0.x, w1p[0], pk2b(0.f));
                u64 a1 = fma2(v0.y, w1p[1], pk2b(0.f));
                a0 = fma2(v1.x, w1p[2], a0);
                a1 = fma2(v1.y, w1p[3], a1);
                float2 f0 = up2(a0), f1 = up2(a1);
                float s = (f0.x + f0.y) + (f1.x + f1.y);
                s += __shfl_xor_sync(0xffffffffu, s, 1);
                s += __shfl_xor_sync(0xffffffffu, s, 2);
                s += __shfl_xor_sync(0xffffffffu, s, 4);
                if (kq8 == 0) S->bufB[bb][n * H + c8] = s;
            }
        }
        __syncthreads();

        // ---- mix1: relu(adjn @ bufB + g1b) -> bufA ----
        if (tid < 448) {
            u64 acc = *(const u64*)(S->g1b + 2 * php);
            #pragma unroll
            for (int j = 0; j < 7; j++)
                acc = fma2(pk2b(S->adjn[pbb][pn * 8 + j]),
                           *(const u64*)(S->bufB[pbb] + j * H + 2 * php), acc);
            float2 a = up2(acc);
            a.x = fmaxf(a.x, 0.f); a.y = fmaxf(a.y, 0.f);
            *(float2*)(S->bufA[pbb] + pn * H + 2 * php) = a;
        }
        __syncthreads();

        // ---- gcn2 GEMM ----
        #pragma unroll
        for (int bb = 0; bb < 2; bb++) {
            #pragma unroll
            for (int n = 0; n < 7; n++) {
                const ulonglong2* xp = reinterpret_cast<const ulonglong2*>(
                    S->bufA[bb] + n * H + kq8 * 8);
                ulonglong2 v0 = xp[0], v1 = xp[1];
                u64 a0 = fma2(v0.x, w2p[0], pk2b(0.f));
                u64 a1 = fma2(v0.y, w2p[1], pk2b(0.f));
                a0 = fma2(v1.x, w2p[2], a0);
                a1 = fma2(v1.y, w2p[3], a1);
                float2 f0 = up2(a0), f1 = up2(a1);
                float s = (f0.x + f0.y) + (f1.x + f1.y);
                s += __shfl_xor_sync(0xffffffffu, s, 1);
                s += __shfl_xor_sync(0xffffffffu, s, 2);
                s += __shfl_xor_sync(0xffffffffu, s, 4);
                if (kq8 == 0) S->bufB[bb][n * H + c8] = s;
            }
        }
        __syncthreads();

        // ---- mix2: relu(adjn @ bufB + g2b) -> bufA (= s2) ----
        if (tid < 448) {
            u64 acc = *(const u64*)(S->g2b + 2 * php);
            #pragma unroll
            for (int j = 0; j < 7; j++)
                acc = fma2(pk2b(S->adjn[pbb][pn * 8 + j]),
                           *(const u64*)(S->bufB[pbb] + j * H + 2 * php), acc);
            float2 a = up2(acc);
            a.x = fmaxf(a.x, 0.f); a.y = fmaxf(a.y, 0.f);
            *(float2*)(S->bufA[pbb] + pn * H + 2 * php) = a;
        }
        __syncthreads();

        // ---- LSTM gates: gbuf = s2 @ w_ih^T + hx @ w_hh^T ----
        {
            const float* srcbase = par ? &S->hx[0][0] : &S->bufA[0][0];
            #pragma unroll
            for (int bb = 0; bb < 2; bb++) {
                #pragma unroll
                for (int n = 0; n < 7; n++) {
                    const ulonglong2* src = reinterpret_cast<const ulonglong2*>(
                        srcbase + bb * (NN * H) + n * H);
                    u64 a0 = pk2b(0.f), a1 = pk2b(0.f);
                    #pragma unroll
                    for (int q = 0; q < 16; q++) {
                        ulonglong2 v = src[q];
                        a0 = fma2(v.x, wl[2 * q], a0);
                        a1 = fma2(v.y, wl[2 * q + 1], a1);
                    }
                    float2 f0 = up2(a0), f1 = up2(a1);
                    float s = (f0.x + f0.y) + (f1.x + f1.y);
                    s += __shfl_xor_sync(0xffffffffu, s, 1);
                    if (bb == par)   // after shfl both lanes hold the full sum
                        S->gbuf[bb][n * G4 + col] = s;
                }
            }
        }
        __syncthreads();

        // ---- LSTM update ----
        if (tid < 448) {
            const float* gb = S->gbuf[pbb] + pn * G4 + 2 * php;
            const float* bs = S->bsum + 2 * php;
            float2 gi = *(const float2*)(gb);
            float2 gf = *(const float2*)(gb + 64);
            float2 gg = *(const float2*)(gb + 128);
            float2 go = *(const float2*)(gb + 192);
            float2 bi = *(const float2*)(bs);
            float2 bf = *(const float2*)(bs + 64);
            float2 bg = *(const float2*)(bs + 128);
            float2 bo = *(const float2*)(bs + 192);
            float2 c  = *(const float2*)(S->cx[pbb] + pn * H + 2 * php);
            float cx0 = sigf(gf.x + bf.x) * c.x + sigf(gi.x + bi.x) * tanhfast(gg.x + bg.x);
            float cx1 = sigf(gf.y + bf.y) * c.y + sigf(gi.y + bi.y) * tanhfast(gg.y + bg.y);
            float2 h;
            h.x = sigf(go.x + bo.x) * tanhfast(cx0);
            h.y = sigf(go.y + bo.y) * tanhfast(cx1);
            *(float2*)(S->cx[pbb] + pn * H + 2 * php) = make_float2(cx0, cx1);
            *(float2*)(S->hx[pbb] + pn * H + 2 * php) = h;
        }
        __syncthreads();

        // ---- decoder (future steps) ----
        if (step >= NT) {
            if (tid < 224) {
                int bb = tid / 112, r = tid % 112, n = r >> 4, jp = r & 15;
                u64 acc = *(const u64*)(S->db1 + 2 * jp);
                const float2* hrow = (const float2*)(S->hx[bb] + n * H);
                #pragma unroll
                for (int kp = 0; kp < 32; kp++) {
                    float2 xv = hrow[kp];
                    acc = fma2(pk2b(xv.x), *(const u64*)(S->dw1 + (2 * kp) * 32 + 2 * jp), acc);
                    acc = fma2(pk2b(xv.y), *(const u64*)(S->dw1 + (2 * kp + 1) * 32 + 2 * jp), acc);
                }
                float2 a = up2(acc);
                a.x = fmaxf(a.x, 0.f); a.y = fmaxf(a.y, 0.f);
                *(float2*)(S->dbuf[bb] + n * 32 + 2 * jp) = a;
            }
            __syncthreads();
            if (tid < 84) {
                int bb = tid / 42, r = tid % 42, n = r / 6, d = r % 6;
                float acc = S->db2[d];
                const float* db = S->dbuf[bb] + n * 32;
                #pragma unroll
                for (int j = 0; j < 32; j++)
                    acc += db[j] * S->dw2[j * DYN + d];
                float p = S->pred[bb][n * DYN + d] + tanhfast(acc) * 0.05f;
                p = fminf(fmaxf(p, 0.f), 1.0f);
                S->pred[bb][n * DYN + d] = p;
                out[(((b0 + bb) * FUT + (step - NT)) * NN + n) * DYN + d] = p;
            }
            __syncthreads();
        }
    }
}

extern "C" void kernel_launch(void* const* d_in, const int* in_sizes, int n_in,
                              void* d_out, int out_size)
{
    (void)in_sizes; (void)n_in; (void)out_size;
    cudaFuncSetAttribute(stgnn_kernel,
                         cudaFuncAttributeMaxDynamicSharedMemorySize,
                         (int)sizeof(Smem));
    stgnn_kernel<<<NB / 2, NTHREADS, sizeof(Smem)>>>(
        (const float*)d_in[0],  (const float*)d_in[1],
        (const float*)d_in[2],  (const float*)d_in[3],
        (const float*)d_in[4],  (const float*)d_in[5],
        (const float*)d_in[6],  (const float*)d_in[7],
        (const float*)d_in[8],  (const float*)d_in[9],
        (const float*)d_in[10], (const float*)d_in[11],
        (const float*)d_in[12], (const float*)d_in[13],
        (const float*)d_in[14], (const float*)d_in[15],
        (float*)d_out);
}

// round 8
// speedup vs baseline: 1.0379x; 1.0379x over previous
#include <cuda_runtime.h>

#define NB   4096
#define NT   24
#define NN   7
#define DYN  6
#define STAT 5
#define NIN  11
#define H    64
#define FUT  48
#define G4   256
#define NTHREADS 512
#define PSTRIDE 452   // partial-array stride (bank-conflict-free padding)

typedef unsigned long long u64;

struct alignas(16) Smem {
    float xhist[NT * 77];    // 1848 — whole history slice for this batch
    float enc_w[NIN * H];    // 704
    float dw1[H * 32];       // 2048
    float dw2[32 * DYN];     // 192
    float enc_b[H];
    float g1b[H];
    float g2b[H];
    float bsum[G4];
    float db1[32];
    float db2[8];
    float adjn[56];          // 7 rows padded to 8 (pad col stores d_i)
    float bufA[NN * H];      // 448
    float bufB[NN * H];
    float hx[NN * H];
    float cx[NN * H];
    float gbuf[NN * G4];     // 1792
    float dbuf[NN * 32];     // 224
    float pred[48];
    float stat[40];
    float part[8 * PSTRIDE]; // 3616 — GCN K-partials
};

__device__ __forceinline__ float sigf(float x) {
    return 1.0f / (1.0f + __expf(-x));
}
__device__ __forceinline__ float tanhfast(float x) {
    return 2.0f / (1.0f + __expf(-2.0f * x)) - 1.0f;
}
__device__ __forceinline__ u64 fma2(u64 a, u64 b, u64 c) {
    u64 d;
    asm("fma.rn.f32x2 %0, %1, %2, %3;" : "=l"(d) : "l"(a), "l"(b), "l"(c));
    return d;
}
__device__ __forceinline__ u64 pk2(float lo, float hi) {
    u64 v;
    asm("mov.b64 %0, {%1, %2};" : "=l"(v) : "f"(lo), "f"(hi));
    return v;
}
__device__ __forceinline__ float2 up2(u64 v) {
    float2 f;
    asm("mov.b64 {%0, %1}, %2;" : "=f"(f.x), "=f"(f.y) : "l"(v));
    return f;
}

__global__ void __launch_bounds__(NTHREADS, 1) stgnn_kernel(
    const float* __restrict__ x_history, const float* __restrict__ adj,
    const float* __restrict__ enc_w, const float* __restrict__ enc_b,
    const float* __restrict__ g1w, const float* __restrict__ g1b,
    const float* __restrict__ g2w, const float* __restrict__ g2b,
    const float* __restrict__ w_ih, const float* __restrict__ w_hh,
    const float* __restrict__ b_ih, const float* __restrict__ b_hh,
    const float* __restrict__ dw1, const float* __restrict__ db1,
    const float* __restrict__ dw2, const float* __restrict__ db2,
    float* __restrict__ out)
{
    extern __shared__ unsigned char smraw[];
    Smem* S = reinterpret_cast<Smem*>(smraw);

    const int tid  = threadIdx.x;
    const int lane = tid & 31;
    const int wrp  = tid >> 5;
    const size_t b = blockIdx.x;

    // ---- stage inputs / small weights into smem ----
    for (int i = tid; i < NT * 77; i += NTHREADS)
        S->xhist[i] = x_history[b * (NT * 77) + i];
    for (int i = tid; i < NIN * H; i += NTHREADS) S->enc_w[i] = enc_w[i];
    for (int i = tid; i < H * 32; i += NTHREADS) S->dw1[i] = dw1[i];
    if (tid < 32 * DYN) S->dw2[tid] = dw2[tid];
    if (tid < H)  { S->enc_b[tid] = enc_b[tid]; S->g1b[tid] = g1b[tid]; S->g2b[tid] = g2b[tid]; }
    if (tid < G4) S->bsum[tid] = b_ih[tid] + b_hh[tid];
    if (tid < 32)  S->db1[tid] = db1[tid];
    if (tid < DYN) S->db2[tid] = db2[tid];

    // ---- adjacency normalize ----
    if (tid < 49) {
        int i = tid / 7, j = tid % 7;
        float v = adj[b * 49 + tid];
        if (i == j) v = 1.0f;
        S->adjn[i * 8 + j] = v;
    }
    // ---- init state ----
    for (int i = tid; i < NN * H; i += NTHREADS) { S->hx[i] = 0.f; S->cx[i] = 0.f; }
    if (tid < 77) {
        int n = tid / NIN, k = tid % NIN;
        float v = x_history[(b * NT + (NT - 1)) * 77 + tid];
        if (k < DYN) S->pred[n * DYN + k] = v;
        else         S->stat[n * STAT + (k - DYN)] = v;
    }
    __syncthreads();
    if (tid < 7) {
        float s = 0.f;
        #pragma unroll
        for (int j = 0; j < 7; j++) s += S->adjn[tid * 8 + j];
        S->adjn[tid * 8 + 7] = rsqrtf(fmaxf(s, 1.0f));
    }
    __syncthreads();
    if (tid < 49) {
        int i = tid / 7, j = tid % 7;
        S->adjn[i * 8 + j] *= S->adjn[i * 8 + 7] * S->adjn[j * 8 + 7];
    }

    // ---- register-cache LSTM weights: (col, par) scheme ----
    const int col = wrp * 16 + (lane >> 1);  // 0..255
    const int par = lane & 1;                // 0: s2@w_ih, 1: hx@w_hh
    u64 wl[32];
    {
        const ulonglong2* wp = reinterpret_cast<const ulonglong2*>(
            (par ? w_hh : w_ih) + (size_t)col * H);
        #pragma unroll
        for (int q = 0; q < 16; q++) {
            ulonglong2 v = wp[q];
            wl[2 * q] = v.x; wl[2 * q + 1] = v.y;
        }
    }

    // ---- register-cache GCN weights: thread = (c8, kq8), 8 k-values each ----
    const int kq8 = tid & 7;
    const int c8  = tid >> 3;
    u64 w1p[4], w2p[4];
    #pragma unroll
    for (int q = 0; q < 4; q++) {
        int k = kq8 * 8 + 2 * q;
        w1p[q] = pk2(g1w[k * H + c8], g1w[(k + 1) * H + c8]);
        w2p[q] = pk2(g2w[k * H + c8], g2w[(k + 1) * H + c8]);
    }
    __syncthreads();

    const int n448 = tid >> 6;   // node for 448-wide phases
    const int h448 = tid & 63;   // feature

    for (int step = 0; step < NT + FUT; ++step) {
        // ---- encoder: relu(x_t @ enc_w + b) -> bufA (x_t from smem) ----
        if (tid < 448) {
            float acc = S->enc_b[h448];
            if (step < NT) {
                const float* xr = S->xhist + step * 77 + n448 * NIN;
                #pragma unroll
                for (int k = 0; k < NIN; k++)
                    acc += xr[k] * S->enc_w[k * H + h448];
            } else {
                #pragma unroll
                for (int k = 0; k < NIN; k++) {
                    float xv = (k < DYN) ? S->pred[n448 * DYN + k]
                                         : S->stat[n448 * STAT + (k - DYN)];
                    acc += xv * S->enc_w[k * H + h448];
                }
            }
            S->bufA[tid] = fmaxf(acc, 0.f);
        }
        __syncthreads();

        // ======== GCN layer 1 ========
        // partial GEMM: all 512 threads, weights in regs, no shuffles
        {
            #pragma unroll
            for (int n = 0; n < 7; n++) {
                const ulonglong2* xp = reinterpret_cast<const ulonglong2*>(
                    S->bufA + n * H + kq8 * 8);
                ulonglong2 v0 = xp[0], v1 = xp[1];
                u64 a0 = fma2(v0.x, w1p[0], 0ull);
                u64 a1 = fma2(v0.y, w1p[1], 0ull);
                a0 = fma2(v1.x, w1p[2], a0);
                a1 = fma2(v1.y, w1p[3], a1);
                float2 f0 = up2(a0), f1 = up2(a1);
                S->part[kq8 * PSTRIDE + n * H + c8] = (f0.x + f0.y) + (f1.x + f1.y);
            }
        }
        __syncthreads();
        // reduce partials -> bufB (plain sum; bias+relu happen after mix)
        if (tid < 448) {
            float t = 0.f;
            #pragma unroll
            for (int kq = 0; kq < 8; kq++) t += S->part[kq * PSTRIDE + tid];
            S->bufB[tid] = t;
        }
        __syncthreads();
        // mix: relu(adjn @ bufB + g1b) -> bufA
        if (tid < 448) {
            float acc = S->g1b[h448];
            #pragma unroll
            for (int j = 0; j < 7; j++)
                acc += S->adjn[n448 * 8 + j] * S->bufB[j * H + h448];
            S->bufA[tid] = fmaxf(acc, 0.f);
        }
        __syncthreads();

        // ======== GCN layer 2 ========
        {
            #pragma unroll
            for (int n = 0; n < 7; n++) {
                const ulonglong2* xp = reinterpret_cast<const ulonglong2*>(
                    S->bufA + n * H + kq8 * 8);
                ulonglong2 v0 = xp[0], v1 = xp[1];
                u64 a0 = fma2(v0.x, w2p[0], 0ull);
                u64 a1 = fma2(v0.y, w2p[1], 0ull);
                a0 = fma2(v1.x, w2p[2], a0);
                a1 = fma2(v1.y, w2p[3], a1);
                float2 f0 = up2(a0), f1 = up2(a1);
                S->part[kq8 * PSTRIDE + n * H + c8] = (f0.x + f0.y) + (f1.x + f1.y);
            }
        }
        __syncthreads();
        if (tid < 448) {
            float t = 0.f;
            #pragma unroll
            for (int kq = 0; kq < 8; kq++) t += S->part[kq * PSTRIDE + tid];
            S->bufB[tid] = t;
        }
        __syncthreads();
        if (tid < 448) {
            float acc = S->g2b[h448];
            #pragma unroll
            for (int j = 0; j < 7; j++)
                acc += S->adjn[n448 * 8 + j] * S->bufB[j * H + h448];
            S->bufA[tid] = fmaxf(acc, 0.f);
        }
        __syncthreads();

        // ---- LSTM gates: gbuf = s2 @ w_ih^T + hx @ w_hh^T ----
        {
            const float* src = par ? S->hx : S->bufA;
            #pragma unroll
            for (int n = 0; n < 7; n++) {
                const ulonglong2* sp = reinterpret_cast<const ulonglong2*>(src + n * H);
                u64 a0 = 0ull, a1 = 0ull;
                #pragma unroll
                for (int q = 0; q < 16; q++) {
                    ulonglong2 v = sp[q];
                    a0 = fma2(v.x, wl[2 * q], a0);
                    a1 = fma2(v.y, wl[2 * q + 1], a1);
                }
                float2 f0 = up2(a0), f1 = up2(a1);
                float s = (f0.x + f0.y) + (f1.x + f1.y);
                s += __shfl_xor_sync(0xffffffffu, s, 1);
                if ((n < 4) == (par == 0))     // split stores across the lane pair
                    S->gbuf[n * G4 + col] = s;
            }
        }
        __syncthreads();

        // ---- LSTM update ----
        if (tid < 448) {
            const float* gb = S->gbuf + n448 * G4 + h448;
            float gi = gb[0]   + S->bsum[h448];
            float gf = gb[64]  + S->bsum[64 + h448];
            float gg = gb[128] + S->bsum[128 + h448];
            float go = gb[192] + S->bsum[192 + h448];
            float c = sigf(gf) * S->cx[tid] + sigf(gi) * tanhfast(gg);
            S->cx[tid] = c;
            S->hx[tid] = sigf(go) * tanhfast(c);
        }
        __syncthreads();

        // ---- decoder (future steps) ----
        if (step >= NT) {
            if (tid < 112) {
                int n = tid >> 4, jp = tid & 15;
                u64 acc = *(const u64*)(S->db1 + 2 * jp);
                const float2* hrow = (const float2*)(S->hx + n * H);
                #pragma unroll
                for (int kp = 0; kp < 32; kp++) {
                    float2 xv = hrow[kp];
                    acc = fma2(pk2(xv.x, xv.x), *(const u64*)(S->dw1 + (2 * kp) * 32 + 2 * jp), acc);
                    acc = fma2(pk2(xv.y, xv.y), *(const u64*)(S->dw1 + (2 * kp + 1) * 32 + 2 * jp), acc);
                }
                float2 a = up2(acc);
                a.x = fmaxf(a.x, 0.f); a.y = fmaxf(a.y, 0.f);
                *(float2*)(S->dbuf + n * 32 + 2 * jp) = a;
            }
            __syncthreads();
            if (tid < 42) {
                int n = tid / 6, d = tid % 6;
                float acc = S->db2[d];
                const float* db = S->dbuf + n * 32;
                #pragma unroll
                for (int j = 0; j < 32; j++)
                    acc += db[j] * S->dw2[j * DYN + d];
                float p = S->pred[tid] + tanhfast(acc) * 0.05f;
                p = fminf(fmaxf(p, 0.f), 1.0f);
                S->pred[tid] = p;
                out[((b * FUT + (step - NT)) * NN + n) * DYN + d] = p;
            }
            __syncthreads();
        }
    }
}

extern "C" void kernel_launch(void* const* d_in, const int* in_sizes, int n_in,
                              void* d_out, int out_size)
{
    (void)in_sizes; (void)n_in; (void)out_size;
    cudaFuncSetAttribute(stgnn_kernel,
                         cudaFuncAttributeMaxDynamicSharedMemorySize,
                         (int)sizeof(Smem));
    stgnn_kernel<<<NB, NTHREADS, sizeof(Smem)>>>(
        (const float*)d_in[0],  (const float*)d_in[1],
        (const float*)d_in[2],  (const float*)d_in[3],
        (const float*)d_in[4],  (const float*)d_in[5],
        (const float*)d_in[6],  (const float*)d_in[7],
        (const float*)d_in[8],  (const float*)d_in[9],
        (const float*)d_in[10], (const float*)d_in[11],
        (const float*)d_in[12], (const float*)d_in[13],
        (const float*)d_in[14], (const float*)d_in[15],
        (float*)d_out);
}

// round 9
// speedup vs baseline: 2.5808x; 2.4865x over previous
#include <cuda_runtime.h>

#define NT   24
#define FUT  48
#define NSTEP (NT + FUT)
#define NW   8            // warps (=batches) per block
#define NTHREADS (NW * 32)
#define GRID (4096 / NW)

typedef unsigned long long u64;

// ---- dynamic smem layout (float offsets) ----
#define OFF_WL    0                      // 512 rows x 64 (w_ih cols 0..255, w_hh 256..511), swizzled
#define OFF_WG    (OFF_WL + 512*64)      // 128 rows x 64 (g1wT rows 0..63, g2wT 64..127), swizzled
#define OFF_WD1   (OFF_WG + 128*64)      // 32 rows x 64 (dw1T), swizzled
#define OFF_EWP   (OFF_WD1 + 32*64)      // 11*32 u64 = 704 floats (enc_w pairs)
#define OFF_DW2   (OFF_EWP + 704)        // 192
#define OFF_ENCB  (OFF_DW2 + 192)        // 32 u64 = 64
#define OFF_G1B   (OFF_ENCB + 64)        // 64
#define OFF_G2B   (OFF_G1B + 64)         // 64
#define OFF_BSUM  (OFF_G2B + 64)         // 256
#define OFF_DB1   (OFF_BSUM + 256)       // 32
#define OFF_DB2   (OFF_DB1 + 32)         // 8
#define OFF_PW    (OFF_DB2 + 8 + 16)     // per-warp regions (align)
#define PW_FLOATS 1280
// per-warp internal offsets
#define PSB   0      // sbuf 448 (enc-out / s1 / s2)
#define PHB   448    // hbuf 448
#define PDB   896    // dbuf 224 (also xs staging for history steps)
#define PADJ  1120   // 56
#define PPRED 1176   // 44
#define PSTAT 1220   // 36
#define SMEM_FLOATS (OFF_PW + NW * PW_FLOATS)

__device__ __forceinline__ float sigf(float x) { return 1.0f / (1.0f + __expf(-x)); }
__device__ __forceinline__ float tanhfast(float x) { return 2.0f / (1.0f + __expf(-2.0f * x)) - 1.0f; }

__device__ __forceinline__ u64 fma2(u64 a, u64 b, u64 c) {
    u64 d;
    asm("fma.rn.f32x2 %0, %1, %2, %3;" : "=l"(d) : "l"(a), "l"(b), "l"(c));
    return d;
}
__device__ __forceinline__ u64 pk2(float lo, float hi) {
    u64 v;
    asm("mov.b64 %0, {%1, %2};" : "=l"(v) : "f"(lo), "f"(hi));
    return v;
}
__device__ __forceinline__ u64 pk2b(float s) { return pk2(s, s); }
__device__ __forceinline__ float2 up2(u64 v) {
    float2 f;
    asm("mov.b64 {%0, %1}, %2;" : "=f"(f.x), "=f"(f.y) : "l"(v));
    return f;
}
__device__ __forceinline__ float hadd(u64 v) { float2 f = up2(v); return f.x + f.y; }

// swizzled word offset for weight rows of 64 floats: quad rotated by row
__device__ __forceinline__ int swz(int row, int k) {
    return row * 64 + (((k >> 2) + row) & 15) * 4 + (k & 3);
}

__global__ void __launch_bounds__(NTHREADS, 1) stgnn_kernel(
    const float* __restrict__ x_history, const float* __restrict__ adj,
    const float* __restrict__ enc_w, const float* __restrict__ enc_b,
    const float* __restrict__ g1w, const float* __restrict__ g1b,
    const float* __restrict__ g2w, const float* __restrict__ g2b,
    const float* __restrict__ w_ih, const float* __restrict__ w_hh,
    const float* __restrict__ b_ih, const float* __restrict__ b_hh,
    const float* __restrict__ dw1, const float* __restrict__ db1,
    const float* __restrict__ dw2, const float* __restrict__ db2,
    float* __restrict__ out)
{
    extern __shared__ float sm[];
    const int tid  = threadIdx.x;
    const int lane = tid & 31;
    const int wrp  = tid >> 5;

    // ================= block-wide weight staging =================
    for (int idx = tid; idx < 512 * 64; idx += NTHREADS) {
        int col = idx >> 6, k = idx & 63;
        float v = (col < 256) ? w_ih[col * 64 + k] : w_hh[(col - 256) * 64 + k];
        sm[OFF_WL + swz(col, k)] = v;
    }
    for (int idx = tid; idx < 64 * 64; idx += NTHREADS) {
        int k = idx >> 6, h = idx & 63;
        sm[OFF_WG + swz(h, k)]      = g1w[k * 64 + h];
        sm[OFF_WG + swz(64 + h, k)] = g2w[k * 64 + h];
    }
    for (int idx = tid; idx < 32 * 64; idx += NTHREADS) {
        int k = idx >> 5, j = idx & 31;
        sm[OFF_WD1 + swz(j, k)] = dw1[k * 32 + j];
    }
    for (int idx = tid; idx < 11 * 32; idx += NTHREADS) {
        int k = idx >> 5, h2 = idx & 31;
        ((u64*)(sm + OFF_EWP))[idx] = pk2(enc_w[k * 64 + h2], enc_w[k * 64 + h2 + 32]);
    }
    if (tid < 192) sm[OFF_DW2 + tid] = dw2[tid];
    if (tid < 32) {
        ((u64*)(sm + OFF_ENCB))[tid] = pk2(enc_b[tid], enc_b[tid + 32]);
        ((u64*)(sm + OFF_G1B))[tid]  = pk2(g1b[tid], g1b[tid + 32]);
        ((u64*)(sm + OFF_G2B))[tid]  = pk2(g2b[tid], g2b[tid + 32]);
        sm[OFF_DB1 + tid] = db1[tid];
    }
    if (tid < 256) sm[OFF_BSUM + tid] = b_ih[tid] + b_hh[tid];
    if (tid < 6)   sm[OFF_DB2 + tid] = db2[tid];
    __syncthreads();   // ONLY block barrier in the kernel

    // ================= per-warp setup =================
    const size_t b = (size_t)blockIdx.x * NW + wrp;
    float* PW   = sm + OFF_PW + wrp * PW_FLOATS;
    float* SB   = PW + PSB;
    float* HB   = PW + PHB;
    float* DB   = PW + PDB;
    float* ADJ  = PW + PADJ;
    float* PRED = PW + PPRED;
    float* STAT = PW + PSTAT;

    // adjacency normalize (warp-local)
    {
        #pragma unroll
        for (int rep = 0; rep < 2; rep++) {
            int e = lane + 32 * rep;
            if (e < 49) {
                int i = e / 7, j = e - 7 * i;
                float v = adj[b * 49 + e];
                if (i == j) v = 1.0f;
                ADJ[i * 8 + j] = v;
            }
        }
        __syncwarp();
        if (lane < 7) {
            float s = 0.f;
            #pragma unroll
            for (int j = 0; j < 7; j++) s += ADJ[lane * 8 + j];
            ADJ[lane * 8 + 7] = rsqrtf(fmaxf(s, 1.0f));
        }
        __syncwarp();
        #pragma unroll
        for (int rep = 0; rep < 2; rep++) {
            int e = lane + 32 * rep;
            if (e < 49) {
                int i = e / 7, j = e - 7 * i;
                ADJ[i * 8 + j] *= ADJ[i * 8 + 7] * ADJ[j * 8 + 7];
            }
        }
        __syncwarp();
    }

    // state init
    float cxr[14];
    #pragma unroll
    for (int i = 0; i < 14; i++) cxr[i] = 0.f;
    #pragma unroll
    for (int n = 0; n < 7; n++) { HB[n * 64 + lane] = 0.f; HB[n * 64 + lane + 32] = 0.f; }
    // pred/stat from last history row
    {
        const float* xl = x_history + (b * NT + (NT - 1)) * 77;
        #pragma unroll
        for (int rep = 0; rep < 3; rep++) {
            int e = lane + 32 * rep;
            if (e < 77) {
                int n = e / 11, k = e - 11 * n;
                float v = xl[e];
                if (k < 6) PRED[n * 6 + k] = v;
                else       STAT[n * 5 + (k - 6)] = v;
            }
        }
        __syncwarp();
    }

    // prefetch history row 0
    float xp0 = 0.f, xp1 = 0.f, xp2 = 0.f;
    {
        const float* xr = x_history + b * NT * 77;
        xp0 = xr[lane];
        xp1 = xr[lane + 32];
        if (lane + 64 < 77) xp2 = xr[lane + 64];
    }

    const float* wl  = sm + OFF_WL;
    const float* wg  = sm + OFF_WG;
    const float* wd1 = sm + OFF_WD1;
    const u64*  ewp  = (const u64*)(sm + OFF_EWP);
    const u64   encb = ((const u64*)(sm + OFF_ENCB))[lane];
    const u64   g1bp = ((const u64*)(sm + OFF_G1B))[lane];
    const u64   g2bp = ((const u64*)(sm + OFF_G2B))[lane];

    // ================= 72-step recurrence (warp-synchronous) =================
    for (int step = 0; step < NSTEP; ++step) {
        // ---- stage x_t (history) into DB; prefetch next row ----
        if (step < NT) {
            DB[lane] = xp0;
            DB[lane + 32] = xp1;
            if (lane + 64 < 77) DB[lane + 64] = xp2;
            __syncwarp();
            if (step + 1 < NT) {
                const float* xr = x_history + (b * NT + step + 1) * 77;
                xp0 = xr[lane];
                xp1 = xr[lane + 32];
                if (lane + 64 < 77) xp2 = xr[lane + 64];
            }
        }

        // ---- encoder: out[n, h(lane), h+32] ----
        {
            u64 eacc[7];
            #pragma unroll
            for (int n = 0; n < 7; n++) eacc[n] = encb;
            if (step < NT) {
                #pragma unroll
                for (int k = 0; k < 11; k++) {
                    u64 wk = ewp[k * 32 + lane];
                    #pragma unroll
                    for (int n = 0; n < 7; n++)
                        eacc[n] = fma2(pk2b(DB[n * 11 + k]), wk, eacc[n]);
                }
            } else {
                #pragma unroll
                for (int k = 0; k < 11; k++) {
                    u64 wk = ewp[k * 32 + lane];
                    #pragma unroll
                    for (int n = 0; n < 7; n++) {
                        float xv = (k < 6) ? PRED[n * 6 + k] : STAT[n * 5 + (k - 6)];
                        eacc[n] = fma2(pk2b(xv), wk, eacc[n]);
                    }
                }
            }
            #pragma unroll
            for (int n = 0; n < 7; n++) {
                float2 a = up2(eacc[n]);
                SB[n * 64 + lane]      = fmaxf(a.x, 0.f);
                SB[n * 64 + lane + 32] = fmaxf(a.y, 0.f);
            }
            __syncwarp();
        }

        // ---- two GCN layers: GEMM (reg accs) + lane-local mix ----
        #pragma unroll
        for (int layer = 0; layer < 2; layer++) {
            const int wrow0 = layer * 64;
            const u64 bp = layer ? g2bp : g1bp;
            u64 ga[14];
            #pragma unroll
            for (int i = 0; i < 14; i++) ga[i] = 0;
            #pragma unroll 4
            for (int q = 0; q < 16; q++) {
                int off = ((q + lane) & 15) * 4;
                ulonglong2 w0 = *(const ulonglong2*)(wl + 0, wg + (wrow0 + lane) * 64 + off);
                ulonglong2 w1 = *(const ulonglong2*)(wg + (wrow0 + lane + 32) * 64 + off);
                #pragma unroll
                for (int n = 0; n < 7; n++) {
                    ulonglong2 a = *(const ulonglong2*)(SB + n * 64 + 4 * q);
                    ga[n * 2]     = fma2(a.y, w0.y, fma2(a.x, w0.x, ga[n * 2]));
                    ga[n * 2 + 1] = fma2(a.y, w1.y, fma2(a.x, w1.x, ga[n * 2 + 1]));
                }
            }
            u64 tp[7];
            #pragma unroll
            for (int j = 0; j < 7; j++) tp[j] = pk2(hadd(ga[j * 2]), hadd(ga[j * 2 + 1]));
            __syncwarp();  // all lanes done reading SB
            #pragma unroll
            for (int n = 0; n < 7; n++) {
                u64 acc = bp;
                #pragma unroll
                for (int j = 0; j < 7; j++)
                    acc = fma2(pk2b(ADJ[n * 8 + j]), tp[j], acc);
                float2 a = up2(acc);
                SB[n * 64 + lane]      = fmaxf(a.x, 0.f);
                SB[n * 64 + lane + 32] = fmaxf(a.y, 0.f);
            }
            __syncwarp();
        }

        // ---- LSTM gates + update ----
        {
            float gif[28];   // pass-0 results: i (jj=0,1), f (jj=2,3) per node
            #pragma unroll
            for (int pass = 0; pass < 2; pass++) {
                const int cbase = lane + 128 * pass;
                u64 gc[28];
                #pragma unroll
                for (int i = 0; i < 28; i++) gc[i] = 0;
                #pragma unroll 4
                for (int q = 0; q < 16; q++) {
                    int off = ((q + lane) & 15) * 4;   // (q+col)&15 == (q+lane)&15 (cols ≡ lane mod 32... mod 16: +128p,+32jj are mult of 16? 32&15=0,128&15=0 ✓)
                    ulonglong2 wi[4], wh[4];
                    #pragma unroll
                    for (int jj = 0; jj < 4; jj++) {
                        int col = cbase + 32 * jj;
                        wi[jj] = *(const ulonglong2*)(wl + col * 64 + off);
                        wh[jj] = *(const ulonglong2*)(wl + (256 + col) * 64 + off);
                    }
                    #pragma unroll
                    for (int n = 0; n < 7; n++) {
                        ulonglong2 sa = *(const ulonglong2*)(SB + n * 64 + 4 * q);
                        ulonglong2 ha = *(const ulonglong2*)(HB + n * 64 + 4 * q);
                        #pragma unroll
                        for (int jj = 0; jj < 4; jj++) {
                            u64 a = gc[n * 4 + jj];
                            a = fma2(sa.x, wi[jj].x, a);
                            a = fma2(sa.y, wi[jj].y, a);
                            a = fma2(ha.x, wh[jj].x, a);
                            a = fma2(ha.y, wh[jj].y, a);
                            gc[n * 4 + jj] = a;
                        }
                    }
                }
                float bb[4];
                #pragma unroll
                for (int jj = 0; jj < 4; jj++) bb[jj] = sm[OFF_BSUM + cbase + 32 * jj];
                if (pass == 0) {
                    #pragma unroll
                    for (int n = 0; n < 7; n++)
                        #pragma unroll
                        for (int jj = 0; jj < 4; jj++)
                            gif[n * 4 + jj] = hadd(gc[n * 4 + jj]) + bb[jj];
                } else {
                    __syncwarp();  // all lanes done reading HB
                    #pragma unroll
                    for (int n = 0; n < 7; n++) {
                        #pragma unroll
                        for (int p = 0; p < 2; p++) {
                            float gi = gif[n * 4 + p];
                            float gf = gif[n * 4 + 2 + p];
                            float gg = hadd(gc[n * 4 + p]) + bb[p];
                            float go = hadd(gc[n * 4 + 2 + p]) + bb[2 + p];
                            float c = sigf(gf) * cxr[n * 2 + p] + sigf(gi) * tanhfast(gg);
                            cxr[n * 2 + p] = c;
                            HB[n * 64 + lane + 32 * p] = sigf(go) * tanhfast(c);
                        }
                    }
                    __syncwarp();
                }
            }
        }

        // ---- decoder (future steps) ----
        if (step >= NT) {
            u64 da[7];
            #pragma unroll
            for (int n = 0; n < 7; n++) da[n] = 0;
            #pragma unroll 4
            for (int q = 0; q < 16; q++) {
                int off = ((q + lane) & 15) * 4;
                ulonglong2 w = *(const ulonglong2*)(wd1 + lane * 64 + off);
                #pragma unroll
                for (int n = 0; n < 7; n++) {
                    ulonglong2 a = *(const ulonglong2*)(HB + n * 64 + 4 * q);
                    da[n] = fma2(a.y, w.y, fma2(a.x, w.x, da[n]));
                }
            }
            float d1b = sm[OFF_DB1 + lane];
            #pragma unroll
            for (int n = 0; n < 7; n++)
                DB[n * 32 + lane] = fmaxf(hadd(da[n]) + d1b, 0.f);
            __syncwarp();

            float* ob = out + (b * FUT + (step - NT)) * 42;
            #pragma unroll
            for (int rep = 0; rep < 2; rep++) {
                int idx = lane + 32 * rep;
                if (idx < 42) {
                    int n = idx / 6, d = idx - 6 * n;
                    float acc = sm[OFF_DB2 + d];
                    const float* dr = DB + n * 32;
                    #pragma unroll
                    for (int j = 0; j < 32; j++)
                        acc += dr[j] * sm[OFF_DW2 + j * 6 + d];
                    float p = PRED[idx] + tanhfast(acc) * 0.05f;
                    p = fminf(fmaxf(p, 0.f), 1.0f);
                    PRED[idx] = p;
                    ob[idx] = p;
                }
            }
            __syncwarp();
        }
    }
}

extern "C" void kernel_launch(void* const* d_in, const int* in_sizes, int n_in,
                              void* d_out, int out_size)
{
    (void)in_sizes; (void)n_in; (void)out_size;
    static_assert(SMEM_FLOATS * 4 < 230000, "smem too big");
    cudaFuncSetAttribute(stgnn_kernel,
                         cudaFuncAttributeMaxDynamicSharedMemorySize,
                         SMEM_FLOATS * 4);
    stgnn_kernel<<<GRID, NTHREADS, SMEM_FLOATS * 4>>>(
        (const float*)d_in[0],  (const float*)d_in[1],
        (const float*)d_in[2],  (const float*)d_in[3],
        (const float*)d_in[4],  (const float*)d_in[5],
        (const float*)d_in[6],  (const float*)d_in[7],
        (const float*)d_in[8],  (const float*)d_in[9],
        (const float*)d_in[10], (const float*)d_in[11],
        (const float*)d_in[12], (const float*)d_in[13],
        (const float*)d_in[14], (const float*)d_in[15],
        (float*)d_out);
}